// round 8
// baseline (speedup 1.0000x reference)
#include <cuda_runtime.h>
#include <math.h>

// IRadon: filtered backprojection.
// Input  x: (4, 1, 363, 180) fp32, layout [n][0][s][a]
// Output:   (4, 1, 256, 256) fp32
//
// Stage 1 (filter_kernel): exact ramp filter h(0)=0.5, h(odd d)=-2/(pi d)^2,
//   h(even)=0. Parity-split samples, 4 outputs/thread, LDS.128-vectorized
//   taps with fully-unrolled compile-time immediate weights (FFMA-imm).
//   Emits slope-form pair table P[n][a][j] = (y[j-1], y[j]-y[j-1]).
// Stage 2 (backproj_kernel): 1 pixel/thread. R5: magic-number floor
//   (FADD.RM) kills the F2I/I2F latency chain, dual accumulators break the
//   serial FFMA chain, unroll 8 doubles loads-in-flight.

#define N_BATCH   4
#define N_THETA   180
#define S_LEN     363          // GRID = ceil(sqrt(2)*256)
#define OUT_W     256
#define PAIR_STRIDE 365        // 363 samples + 1 zero pad each side
#define PI_D 3.14159265358979323846

// Scratch (allocation-free rule: __device__ globals).
__device__ float2 g_pairs[N_BATCH * N_THETA * PAIR_STRIDE];  // ~2.1 MB

struct TrigArgs { float2 cs[N_THETA]; };   // 1440 B, by-value kernel arg

// ---------------------------------------------------------------------------
// Stage 1: ramp filter, one (n,a) column per block, 96 threads.
// ---------------------------------------------------------------------------
#define FPAD 184            // left guard (zeros) in parity arrays
#define FARR 560            // 184 + 364 + slack, 16B-aligned

__global__ __launch_bounds__(96) void filter_kernel(const float* __restrict__ x)
{
    const int a = blockIdx.x;
    const int n = blockIdx.y;
    const int tid = threadIdx.x;

    __shared__ __align__(16) float so [FARR];  // so [FPAD+j] = x[2j+1]
    __shared__ __align__(16) float se [FARR];  // se [FPAD+j] = x[2j]
    __shared__ __align__(16) float se1[FARR];  // se1[FPAD+j] = x[2j+2]
    __shared__ float ys[368];                  // ys[1+i] = y[i]; guards zero

    for (int i = tid; i < FARR; i += 96) { so[i] = 0.f; se[i] = 0.f; se1[i] = 0.f; }
    for (int i = tid; i < 368;  i += 96) ys[i] = 0.f;
    __syncthreads();

    for (int s = tid; s < S_LEN; s += 96) {
        float v = x[((size_t)n * S_LEN + s) * N_THETA + a];
        if (s & 1) so[FPAD + (s >> 1)] = v;
        else {
            se [FPAD + (s >> 1)]     = v;
            se1[FPAD + (s >> 1) - 1] = v;
        }
    }
    __syncthreads();

    const bool groupB = (tid >= 48);
    const int  u      = groupB ? (tid - 48) : tid;
    const bool active = (u < 46) && (tid < 94);

    if (active) {
        const float* __restrict__ arr  = groupB ? se1 : so;
        const float* __restrict__ self = groupB ? so  : se;
        const float* base = arr + FPAD + 4 * u;

        float acc0 = 0.5f * self[FPAD + 4 * u + 0];
        float acc1 = 0.5f * self[FPAD + 4 * u + 1];
        float acc2 = 0.5f * self[FPAD + 4 * u + 2];
        float acc3 = 0.5f * self[FPAD + 4 * u + 3];

        #pragma unroll
        for (int it = 0; it < 92; it++) {
            const int T = -184 + 4 * it;
            const float4 V = *reinterpret_cast<const float4*>(base + T);
            #pragma unroll
            for (int e = 0; e < 4; e++) {
                const float ve = (e == 0) ? V.x : (e == 1) ? V.y : (e == 2) ? V.z : V.w;
                {   const int d = 2 * (T + e - 0) + 1;
                    acc0 = fmaf(ve, (float)(-2.0 / (PI_D * PI_D * (double)d * (double)d)), acc0); }
                {   const int d = 2 * (T + e - 1) + 1;
                    acc1 = fmaf(ve, (float)(-2.0 / (PI_D * PI_D * (double)d * (double)d)), acc1); }
                {   const int d = 2 * (T + e - 2) + 1;
                    acc2 = fmaf(ve, (float)(-2.0 / (PI_D * PI_D * (double)d * (double)d)), acc2); }
                {   const int d = 2 * (T + e - 3) + 1;
                    acc3 = fmaf(ve, (float)(-2.0 / (PI_D * PI_D * (double)d * (double)d)), acc3); }
            }
        }

        const int m0 = 4 * u;
        const int ib = groupB ? 1 : 0;
        const int lim = groupB ? 180 : 181;
        if (m0 + 0 <= lim) ys[1 + 2 * (m0 + 0) + ib] = acc0;
        if (m0 + 1 <= lim) ys[1 + 2 * (m0 + 1) + ib] = acc1;
        if (m0 + 2 <= lim) ys[1 + 2 * (m0 + 2) + ib] = acc2;
        if (m0 + 3 <= lim) ys[1 + 2 * (m0 + 3) + ib] = acc3;
    }
    __syncthreads();

    float2* out = g_pairs + ((size_t)n * N_THETA + a) * PAIR_STRIDE;
    for (int j = tid; j < PAIR_STRIDE; j += 96)
        out[j] = make_float2(ys[j], ys[j + 1] - ys[j]);
}

// ---------------------------------------------------------------------------
// Stage 2: backprojection, 1 pixel/thread, block (32,8), grid (8,32,4).
// pos = px*cos - py*sin + 181; slope-form branch-free lerp.
// Floor via magic number: t = RD(pos + 1.5*2^23); floor f32 = t - magic,
// index bits = float_as_int(t) - 0x4B400000 (exact for |pos| < 2^22).
// ---------------------------------------------------------------------------
#define MAGIC_F   12582912.0f          // 1.5 * 2^23
#define MAGIC_I   0x4B400000

__global__ __launch_bounds__(256) void backproj_kernel(
    float* __restrict__ out, const __grid_constant__ TrigArgs trig)
{
    const int n  = blockIdx.z;
    const int xg = blockIdx.x * 32 + threadIdx.x;        // output col 0..255
    const int yg = blockIdx.y * 8  + threadIdx.y;        // output row 0..255

    // grid coords relative to center: (idx + 53) - 181 = idx - 128
    const float px = (float)(xg - 128);
    const float py = (float)(yg - 128);

    float acc_e = 0.0f, acc_o = 0.0f;
    const float2* __restrict__ col0 = g_pairs + (size_t)n * (N_THETA * PAIR_STRIDE);

    #pragma unroll 4
    for (int a = 0; a < N_THETA; a += 2) {
        {   // even angle
            const float2 cs = trig.cs[a];                          // ULDC
            const float pos = fmaf(px, cs.x, fmaf(-py, cs.y, 181.0f));
            const float t   = __fadd_rd(pos, MAGIC_F);             // FADD.RM
            const float f   = pos - (t - MAGIC_F);                 // pos - floor(pos)
            const int   i   = __float_as_int(t) - MAGIC_I;         // in [-1, 362]
            const float2 v  = __ldg(&col0[(size_t)a * PAIR_STRIDE + (i + 1)]);
            acc_e = fmaf(f, v.y, acc_e + v.x);
        }
        {   // odd angle
            const float2 cs = trig.cs[a + 1];
            const float pos = fmaf(px, cs.x, fmaf(-py, cs.y, 181.0f));
            const float t   = __fadd_rd(pos, MAGIC_F);
            const float f   = pos - (t - MAGIC_F);
            const int   i   = __float_as_int(t) - MAGIC_I;
            const float2 v  = __ldg(&col0[(size_t)(a + 1) * PAIR_STRIDE + (i + 1)]);
            acc_o = fmaf(f, v.y, acc_o + v.x);
        }
    }

    const float SCALE = (float)(PI_D / 360.0);            // pi / (2*180)
    out[((size_t)n * OUT_W + yg) * OUT_W + xg] = (acc_e + acc_o) * SCALE;
}

// ---------------------------------------------------------------------------
extern "C" void kernel_launch(void* const* d_in, const int* in_sizes, int n_in,
                              void* d_out, int out_size)
{
    const float* x = (const float*)d_in[0];
    float* out = (float*)d_out;

    TrigArgs trig;
    for (int a = 0; a < N_THETA; a++) {
        double th = (double)a * (PI_D / 180.0);
        trig.cs[a] = make_float2((float)cos(th), (float)sin(th));
    }

    filter_kernel<<<dim3(N_THETA, N_BATCH), 96>>>(x);
    backproj_kernel<<<dim3(OUT_W / 32, OUT_W / 8, N_BATCH), dim3(32, 8, 1)>>>(out, trig);
}

// round 10
// speedup vs baseline: 1.0942x; 1.0942x over previous
#include <cuda_runtime.h>
#include <math.h>

// IRadon: filtered backprojection.
// Input  x: (4, 1, 363, 180) fp32, layout [n][0][s][a]
// Output:   (4, 1, 256, 256) fp32
//
// Stage 1 (filter_kernel): exact ramp filter h(0)=0.5, h(odd d)=-2/(pi d)^2,
//   h(even)=0. Parity-split samples, 4 outputs/thread, LDS.128-vectorized
//   taps with fully-unrolled compile-time immediate weights (FFMA-imm).
//   R8: emits batch-interleaved slope table
//     g_pairs4[g][a][j] = (y[j-1]_{n=2g}, dy[j-1]_{n=2g}, y[j-1]_{n=2g+1}, dy[j-1]_{n=2g+1})
// Stage 2 (backproj_kernel): R8: one thread serves ONE pixel for TWO batch
//   images — identical geometry (pos/floor/f/address) computed once, one
//   LDG.128 fetches both batches' (y,dy) pairs. ~2x fewer instructions per
//   sample. R5's magic-floor reverted (it bloated the ALU stream).

#define N_BATCH   4
#define N_THETA   180
#define S_LEN     363          // GRID = ceil(sqrt(2)*256)
#define OUT_W     256
#define PAIR_STRIDE 365        // 363 samples + 1 zero pad each side
#define PI_D 3.14159265358979323846

// Scratch (allocation-free rule: __device__ globals).
// [2 batch-groups][N_THETA][PAIR_STRIDE] float4 -> 2.1 MB, L2-resident.
__device__ float4 g_pairs4[2 * N_THETA * PAIR_STRIDE];

struct TrigArgs { float2 cs[N_THETA]; };   // 1440 B, by-value kernel arg

// ---------------------------------------------------------------------------
// Stage 1: ramp filter, one (n,a) column per block, 96 threads.
// ---------------------------------------------------------------------------
#define FPAD 184            // left guard (zeros) in parity arrays
#define FARR 560            // 184 + 364 + slack, 16B-aligned

__global__ __launch_bounds__(96) void filter_kernel(const float* __restrict__ x)
{
    const int a = blockIdx.x;
    const int n = blockIdx.y;
    const int tid = threadIdx.x;

    __shared__ __align__(16) float so [FARR];  // so [FPAD+j] = x[2j+1]
    __shared__ __align__(16) float se [FARR];  // se [FPAD+j] = x[2j]
    __shared__ __align__(16) float se1[FARR];  // se1[FPAD+j] = x[2j+2]
    __shared__ float ys[368];                  // ys[1+i] = y[i]; guards zero

    for (int i = tid; i < FARR; i += 96) { so[i] = 0.f; se[i] = 0.f; se1[i] = 0.f; }
    for (int i = tid; i < 368;  i += 96) ys[i] = 0.f;
    __syncthreads();

    for (int s = tid; s < S_LEN; s += 96) {
        float v = x[((size_t)n * S_LEN + s) * N_THETA + a];
        if (s & 1) so[FPAD + (s >> 1)] = v;
        else {
            se [FPAD + (s >> 1)]     = v;
            se1[FPAD + (s >> 1) - 1] = v;
        }
    }
    __syncthreads();

    const bool groupB = (tid >= 48);
    const int  u      = groupB ? (tid - 48) : tid;
    const bool active = (u < 46) && (tid < 94);

    if (active) {
        const float* __restrict__ arr  = groupB ? se1 : so;
        const float* __restrict__ self = groupB ? so  : se;
        const float* base = arr + FPAD + 4 * u;

        float acc0 = 0.5f * self[FPAD + 4 * u + 0];
        float acc1 = 0.5f * self[FPAD + 4 * u + 1];
        float acc2 = 0.5f * self[FPAD + 4 * u + 2];
        float acc3 = 0.5f * self[FPAD + 4 * u + 3];

        #pragma unroll
        for (int it = 0; it < 92; it++) {
            const int T = -184 + 4 * it;
            const float4 V = *reinterpret_cast<const float4*>(base + T);
            #pragma unroll
            for (int e = 0; e < 4; e++) {
                const float ve = (e == 0) ? V.x : (e == 1) ? V.y : (e == 2) ? V.z : V.w;
                {   const int d = 2 * (T + e - 0) + 1;
                    acc0 = fmaf(ve, (float)(-2.0 / (PI_D * PI_D * (double)d * (double)d)), acc0); }
                {   const int d = 2 * (T + e - 1) + 1;
                    acc1 = fmaf(ve, (float)(-2.0 / (PI_D * PI_D * (double)d * (double)d)), acc1); }
                {   const int d = 2 * (T + e - 2) + 1;
                    acc2 = fmaf(ve, (float)(-2.0 / (PI_D * PI_D * (double)d * (double)d)), acc2); }
                {   const int d = 2 * (T + e - 3) + 1;
                    acc3 = fmaf(ve, (float)(-2.0 / (PI_D * PI_D * (double)d * (double)d)), acc3); }
            }
        }

        const int m0 = 4 * u;
        const int ib = groupB ? 1 : 0;
        const int lim = groupB ? 180 : 181;
        if (m0 + 0 <= lim) ys[1 + 2 * (m0 + 0) + ib] = acc0;
        if (m0 + 1 <= lim) ys[1 + 2 * (m0 + 1) + ib] = acc1;
        if (m0 + 2 <= lim) ys[1 + 2 * (m0 + 2) + ib] = acc2;
        if (m0 + 3 <= lim) ys[1 + 2 * (m0 + 3) + ib] = acc3;
    }
    __syncthreads();

    // Batch-interleaved slope table: this (n,a) column owns one float2 half
    // of each float4 entry [g][a][j]; halves are written by disjoint blocks.
    float2* out = reinterpret_cast<float2*>(
                      &g_pairs4[((size_t)(n >> 1) * N_THETA + a) * PAIR_STRIDE])
                  + (n & 1);
    for (int j = tid; j < PAIR_STRIDE; j += 96)
        out[2 * j] = make_float2(ys[j], ys[j + 1] - ys[j]);
}

// ---------------------------------------------------------------------------
// Stage 2: backprojection. One thread = one pixel x two batch images.
// Block (32,8), grid (8, 32, 2 batch-groups) -> 4096 warps.
// pos = px*cos - py*sin + 181; one LDG.128 per angle serves both batches.
// ---------------------------------------------------------------------------
__global__ __launch_bounds__(256) void backproj_kernel(
    float* __restrict__ out, const __grid_constant__ TrigArgs trig)
{
    const int g  = blockIdx.z;                           // batches 2g, 2g+1
    const int xg = blockIdx.x * 32 + threadIdx.x;        // output col 0..255
    const int yg = blockIdx.y * 8  + threadIdx.y;        // output row 0..255

    // grid coords relative to center: (idx + 53) - 181 = idx - 128
    const float px = (float)(xg - 128);
    const float py = (float)(yg - 128);

    float acc0 = 0.0f, acc1 = 0.0f;
    const float4* __restrict__ col =
        g_pairs4 + (size_t)g * (N_THETA * PAIR_STRIDE);

    #pragma unroll 4
    for (int a = 0; a < N_THETA; a++) {
        const float2 cs = trig.cs[a];                    // const bank
        const float pos = fmaf(px, cs.x, fmaf(-py, cs.y, 181.0f));
        const int   i   = __float2int_rd(pos);           // in [-1, 362]
        const float f   = pos - (float)i;
        const float4 v  = __ldg(&col[i + 1]);            // (y0,dy0,y1,dy1)
        acc0 = fmaf(f, v.y, acc0 + v.x);
        acc1 = fmaf(f, v.w, acc1 + v.z);
        col += PAIR_STRIDE;
    }

    const float SCALE = (float)(PI_D / 360.0);           // pi / (2*180)
    const size_t pix = (size_t)yg * OUT_W + xg;
    out[(size_t)(2 * g)     * (OUT_W * OUT_W) + pix] = acc0 * SCALE;
    out[(size_t)(2 * g + 1) * (OUT_W * OUT_W) + pix] = acc1 * SCALE;
}

// ---------------------------------------------------------------------------
extern "C" void kernel_launch(void* const* d_in, const int* in_sizes, int n_in,
                              void* d_out, int out_size)
{
    const float* x = (const float*)d_in[0];
    float* out = (float*)d_out;

    TrigArgs trig;
    for (int a = 0; a < N_THETA; a++) {
        double th = (double)a * (PI_D / 180.0);
        trig.cs[a] = make_float2((float)cos(th), (float)sin(th));
    }

    filter_kernel<<<dim3(N_THETA, N_BATCH), 96>>>(x);
    backproj_kernel<<<dim3(OUT_W / 32, OUT_W / 8, 2), dim3(32, 8, 1)>>>(out, trig);
}

// round 15
// speedup vs baseline: 1.4900x; 1.3617x over previous
#include <cuda_runtime.h>
#include <math.h>

// IRadon: filtered backprojection.
// Input  x: (4, 1, 363, 180) fp32, layout [n][0][s][a]
// Output:   (4, 1, 256, 256) fp32
//
// Stage 1 (filter_kernel): exact ramp filter h(0)=0.5, h(odd d)=-2/(pi d)^2,
//   h(even)=0. Parity-split samples, 4 outputs/thread, LDS.128-vectorized
//   taps with fully-unrolled compile-time immediate weights (FFMA-imm).
//   Emits batch-interleaved slope table
//     g_pairs4[g][a][j] = (y_{2g}, dy_{2g}, y_{2g+1}, dy_{2g+1})[j-1]
// Stage 2 (backproj_kernel): one thread = one pixel x two batches x HALF the
//   angles (R10: angle split across gridDim.z restores 8192 warps — R8 kept
//   the instruction win but starved the SMs at 4096 warps / issue 22%).
//   Partials go to g_partial; Stage 3 (combine_kernel) sums halves + scales.

#define N_BATCH   4
#define N_THETA   180
#define S_LEN     363          // GRID = ceil(sqrt(2)*256)
#define OUT_W     256
#define N_PIX     (OUT_W * OUT_W)
#define PAIR_STRIDE 365        // 363 samples + 1 zero pad each side
#define PI_D 3.14159265358979323846

// Scratch (allocation-free rule: __device__ globals).
__device__ float4 g_pairs4[2 * N_THETA * PAIR_STRIDE];   // ~2.1 MB, L2-resident
__device__ float2 g_partial[2][2][N_PIX];                // [group][anglehalf][pix]

struct TrigArgs { float2 cs[N_THETA]; };   // 1440 B, by-value kernel arg

// ---------------------------------------------------------------------------
// Stage 1: ramp filter, one (n,a) column per block, 96 threads.
// ---------------------------------------------------------------------------
#define FPAD 184            // left guard (zeros) in parity arrays
#define FARR 560            // 184 + 364 + slack, 16B-aligned

__global__ __launch_bounds__(96) void filter_kernel(const float* __restrict__ x)
{
    const int a = blockIdx.x;
    const int n = blockIdx.y;
    const int tid = threadIdx.x;

    __shared__ __align__(16) float so [FARR];  // so [FPAD+j] = x[2j+1]
    __shared__ __align__(16) float se [FARR];  // se [FPAD+j] = x[2j]
    __shared__ __align__(16) float se1[FARR];  // se1[FPAD+j] = x[2j+2]
    __shared__ float ys[368];                  // ys[1+i] = y[i]; guards zero

    for (int i = tid; i < FARR; i += 96) { so[i] = 0.f; se[i] = 0.f; se1[i] = 0.f; }
    for (int i = tid; i < 368;  i += 96) ys[i] = 0.f;
    __syncthreads();

    for (int s = tid; s < S_LEN; s += 96) {
        float v = x[((size_t)n * S_LEN + s) * N_THETA + a];
        if (s & 1) so[FPAD + (s >> 1)] = v;
        else {
            se [FPAD + (s >> 1)]     = v;
            se1[FPAD + (s >> 1) - 1] = v;
        }
    }
    __syncthreads();

    const bool groupB = (tid >= 48);
    const int  u      = groupB ? (tid - 48) : tid;
    const bool active = (u < 46) && (tid < 94);

    if (active) {
        const float* __restrict__ arr  = groupB ? se1 : so;
        const float* __restrict__ self = groupB ? so  : se;
        const float* base = arr + FPAD + 4 * u;

        float acc0 = 0.5f * self[FPAD + 4 * u + 0];
        float acc1 = 0.5f * self[FPAD + 4 * u + 1];
        float acc2 = 0.5f * self[FPAD + 4 * u + 2];
        float acc3 = 0.5f * self[FPAD + 4 * u + 3];

        #pragma unroll
        for (int it = 0; it < 92; it++) {
            const int T = -184 + 4 * it;
            const float4 V = *reinterpret_cast<const float4*>(base + T);
            #pragma unroll
            for (int e = 0; e < 4; e++) {
                const float ve = (e == 0) ? V.x : (e == 1) ? V.y : (e == 2) ? V.z : V.w;
                {   const int d = 2 * (T + e - 0) + 1;
                    acc0 = fmaf(ve, (float)(-2.0 / (PI_D * PI_D * (double)d * (double)d)), acc0); }
                {   const int d = 2 * (T + e - 1) + 1;
                    acc1 = fmaf(ve, (float)(-2.0 / (PI_D * PI_D * (double)d * (double)d)), acc1); }
                {   const int d = 2 * (T + e - 2) + 1;
                    acc2 = fmaf(ve, (float)(-2.0 / (PI_D * PI_D * (double)d * (double)d)), acc2); }
                {   const int d = 2 * (T + e - 3) + 1;
                    acc3 = fmaf(ve, (float)(-2.0 / (PI_D * PI_D * (double)d * (double)d)), acc3); }
            }
        }

        const int m0 = 4 * u;
        const int ib = groupB ? 1 : 0;
        const int lim = groupB ? 180 : 181;
        if (m0 + 0 <= lim) ys[1 + 2 * (m0 + 0) + ib] = acc0;
        if (m0 + 1 <= lim) ys[1 + 2 * (m0 + 1) + ib] = acc1;
        if (m0 + 2 <= lim) ys[1 + 2 * (m0 + 2) + ib] = acc2;
        if (m0 + 3 <= lim) ys[1 + 2 * (m0 + 3) + ib] = acc3;
    }
    __syncthreads();

    // Batch-interleaved slope table: (n,a) owns one float2 half of each
    // float4 entry [g][a][j]; halves written by disjoint blocks.
    float2* out = reinterpret_cast<float2*>(
                      &g_pairs4[((size_t)(n >> 1) * N_THETA + a) * PAIR_STRIDE])
                  + (n & 1);
    for (int j = tid; j < PAIR_STRIDE; j += 96)
        out[2 * j] = make_float2(ys[j], ys[j + 1] - ys[j]);
}

// ---------------------------------------------------------------------------
// Stage 2: backprojection. One thread = one pixel x two batches x 90 angles.
// Block (32,8), grid (8, 32, 4): z = 2*g + h (batch group g, angle half h).
// 8192 warps. pos = px*cos - py*sin + 181; slope-form branch-free lerp,
// one LDG.128 per angle serves both batches.
// ---------------------------------------------------------------------------
__global__ __launch_bounds__(256) void backproj_kernel(
    const __grid_constant__ TrigArgs trig)
{
    const int g  = blockIdx.z >> 1;                      // batch group
    const int h  = blockIdx.z & 1;                       // angle half
    const int xg = blockIdx.x * 32 + threadIdx.x;        // output col 0..255
    const int yg = blockIdx.y * 8  + threadIdx.y;        // output row 0..255

    // grid coords relative to center: (idx + 53) - 181 = idx - 128
    const float px = (float)(xg - 128);
    const float py = (float)(yg - 128);

    float acc0 = 0.0f, acc1 = 0.0f;
    const float4* __restrict__ col =
        g_pairs4 + ((size_t)g * N_THETA + (size_t)h * 90) * PAIR_STRIDE;
    const int a0 = h * 90;

    #pragma unroll 5
    for (int k = 0; k < 90; k++) {
        const float2 cs = trig.cs[a0 + k];               // const bank
        const float pos = fmaf(px, cs.x, fmaf(-py, cs.y, 181.0f));
        const int   i   = __float2int_rd(pos);           // in [-1, 362]
        const float f   = pos - (float)i;
        const float4 v  = __ldg(&col[i + 1]);            // (y0,dy0,y1,dy1)
        acc0 = fmaf(f, v.y, acc0 + v.x);
        acc1 = fmaf(f, v.w, acc1 + v.z);
        col += PAIR_STRIDE;
    }

    g_partial[g][h][(size_t)yg * OUT_W + xg] = make_float2(acc0, acc1);
}

// ---------------------------------------------------------------------------
// Stage 3: combine the two angle halves + scale. 65536 threads, 1 pix each.
// ---------------------------------------------------------------------------
__global__ __launch_bounds__(256) void combine_kernel(float* __restrict__ out)
{
    const int pix = blockIdx.x * 256 + threadIdx.x;
    const float SCALE = (float)(PI_D / 360.0);           // pi / (2*180)

    const float2 p00 = g_partial[0][0][pix];
    const float2 p01 = g_partial[0][1][pix];
    const float2 p10 = g_partial[1][0][pix];
    const float2 p11 = g_partial[1][1][pix];

    out[0 * N_PIX + pix] = (p00.x + p01.x) * SCALE;
    out[1 * N_PIX + pix] = (p00.y + p01.y) * SCALE;
    out[2 * N_PIX + pix] = (p10.x + p11.x) * SCALE;
    out[3 * N_PIX + pix] = (p10.y + p11.y) * SCALE;
}

// ---------------------------------------------------------------------------
extern "C" void kernel_launch(void* const* d_in, const int* in_sizes, int n_in,
                              void* d_out, int out_size)
{
    const float* x = (const float*)d_in[0];
    float* out = (float*)d_out;

    TrigArgs trig;
    for (int a = 0; a < N_THETA; a++) {
        double th = (double)a * (PI_D / 180.0);
        trig.cs[a] = make_float2((float)cos(th), (float)sin(th));
    }

    filter_kernel<<<dim3(N_THETA, N_BATCH), 96>>>(x);
    backproj_kernel<<<dim3(OUT_W / 32, OUT_W / 8, 4), dim3(32, 8, 1)>>>(trig);
    combine_kernel<<<N_PIX / 256, 256>>>(out);
}

// round 17
// speedup vs baseline: 1.5736x; 1.0561x over previous
#include <cuda_runtime.h>
#include <math.h>

// IRadon: filtered backprojection.
// Input  x: (4, 1, 363, 180) fp32, layout [n][0][s][a]
// Output:   (4, 1, 256, 256) fp32
//
// Stage 1 (filter_kernel): exact ramp filter h(0)=0.5, h(odd d)=-2/(pi d)^2,
//   h(even)=0. Parity-split samples, 4 outputs/thread, LDS.128-vectorized
//   taps with compile-time immediate weights. R15: tap range split across two
//   warp-aligned half-blocks (192 threads) -> 2x warps (filter was occ 20%,
//   warp-starved at 96 threads/block). Partial sums combined through smem.
//   Emits batch-interleaved slope table
//     g_pairs4[g][a][j] = (y_{2g}, dy_{2g}, y_{2g+1}, dy_{2g+1})[j-1]
// Stage 2 (backproj_kernel): one thread = one pixel x two batches x 90 angles
//   (angle halves across gridDim.z; 8192 warps). One LDG.128 per angle
//   serves both batches. Stage 3 (combine_kernel) sums halves + scales.

#define N_BATCH   4
#define N_THETA   180
#define S_LEN     363          // GRID = ceil(sqrt(2)*256)
#define OUT_W     256
#define N_PIX     (OUT_W * OUT_W)
#define PAIR_STRIDE 365        // 363 samples + 1 zero pad each side
#define PI_D 3.14159265358979323846

// Scratch (allocation-free rule: __device__ globals).
__device__ float4 g_pairs4[2 * N_THETA * PAIR_STRIDE];   // ~2.1 MB, L2-resident
__device__ float2 g_partial[2][2][N_PIX];                // [group][anglehalf][pix]

struct TrigArgs { float2 cs[N_THETA]; };   // 1440 B, by-value kernel arg

// ---------------------------------------------------------------------------
// Stage 1: ramp filter, one (n,a) column per block, 192 threads.
//   warps 0-2: taps T in [-184,-4];  warps 3-5: taps T in [0,180] + self term.
//   Within each 96-thread half: tid%96 < 48 -> even outputs, else odd.
// ---------------------------------------------------------------------------
#define FPAD 184            // left guard (zeros) in parity arrays
#define FARR 560            // 184 + 364 + slack, 16B-aligned

// One float4 tap-group: 4 samples feed 4 accumulators with immediate weights.
#define TAP_BODY(Tc)                                                           \
    {                                                                          \
        const float4 V = *reinterpret_cast<const float4*>(base + (Tc));        \
        _Pragma("unroll")                                                      \
        for (int e = 0; e < 4; e++) {                                          \
            const float ve = (e == 0) ? V.x : (e == 1) ? V.y                   \
                              : (e == 2) ? V.z : V.w;                          \
            {   const int d = 2 * ((Tc) + e - 0) + 1;                          \
                acc0 = fmaf(ve, (float)(-2.0/(PI_D*PI_D*(double)d*(double)d)), acc0); } \
            {   const int d = 2 * ((Tc) + e - 1) + 1;                          \
                acc1 = fmaf(ve, (float)(-2.0/(PI_D*PI_D*(double)d*(double)d)), acc1); } \
            {   const int d = 2 * ((Tc) + e - 2) + 1;                          \
                acc2 = fmaf(ve, (float)(-2.0/(PI_D*PI_D*(double)d*(double)d)), acc2); } \
            {   const int d = 2 * ((Tc) + e - 3) + 1;                          \
                acc3 = fmaf(ve, (float)(-2.0/(PI_D*PI_D*(double)d*(double)d)), acc3); } \
        }                                                                      \
    }

__global__ __launch_bounds__(192) void filter_kernel(const float* __restrict__ x)
{
    const int a = blockIdx.x;
    const int n = blockIdx.y;
    const int tid = threadIdx.x;

    __shared__ __align__(16) float so [FARR];  // so [FPAD+j] = x[2j+1]
    __shared__ __align__(16) float se [FARR];  // se [FPAD+j] = x[2j]
    __shared__ __align__(16) float se1[FARR];  // se1[FPAD+j] = x[2j+2]
    __shared__ float ys[368];                  // ys[1+i] = y[i]; guards zero
    __shared__ __align__(16) float part[2][188];  // lower-half partials

    for (int i = tid; i < FARR; i += 192) { so[i] = 0.f; se[i] = 0.f; se1[i] = 0.f; }
    for (int i = tid; i < 368;  i += 192) ys[i] = 0.f;
    __syncthreads();

    for (int s = tid; s < S_LEN; s += 192) {
        float v = x[((size_t)n * S_LEN + s) * N_THETA + a];
        if (s & 1) so[FPAD + (s >> 1)] = v;
        else {
            se [FPAD + (s >> 1)]     = v;
            se1[FPAD + (s >> 1) - 1] = v;
        }
    }
    __syncthreads();

    const int  half   = tid / 96;              // warp-uniform (warps 0-2 / 3-5)
    const int  t96    = tid % 96;
    const bool groupB = (t96 >= 48);
    const int  u      = groupB ? (t96 - 48) : t96;
    const bool active = (u < 46);
    const int  ib     = groupB ? 1 : 0;
    const int  m0     = 4 * u;

    float acc0 = 0.f, acc1 = 0.f, acc2 = 0.f, acc3 = 0.f;

    if (active) {
        const float* __restrict__ arr = groupB ? se1 : so;
        const float* base = arr + FPAD + m0;

        if (half == 0) {
            #pragma unroll
            for (int it = 0; it < 46; it++) TAP_BODY(-184 + 4 * it)
        } else {
            #pragma unroll
            for (int it = 46; it < 92; it++) TAP_BODY(-184 + 4 * it)
        }
    }

    if (active && half == 0)
        *reinterpret_cast<float4*>(&part[ib][m0]) = make_float4(acc0, acc1, acc2, acc3);
    __syncthreads();

    if (active && half == 1) {
        const float* __restrict__ self = groupB ? so : se;
        const float4 p = *reinterpret_cast<const float4*>(&part[ib][m0]);
        const float4 s4 = *reinterpret_cast<const float4*>(&self[FPAD + m0]);
        acc0 += p.x + 0.5f * s4.x;
        acc1 += p.y + 0.5f * s4.y;
        acc2 += p.z + 0.5f * s4.z;
        acc3 += p.w + 0.5f * s4.w;

        const int lim = groupB ? 180 : 181;
        if (m0 + 0 <= lim) ys[1 + 2 * (m0 + 0) + ib] = acc0;
        if (m0 + 1 <= lim) ys[1 + 2 * (m0 + 1) + ib] = acc1;
        if (m0 + 2 <= lim) ys[1 + 2 * (m0 + 2) + ib] = acc2;
        if (m0 + 3 <= lim) ys[1 + 2 * (m0 + 3) + ib] = acc3;
    }
    __syncthreads();

    // Batch-interleaved slope table: (n,a) owns one float2 half of each
    // float4 entry [g][a][j]; halves written by disjoint blocks.
    float2* out = reinterpret_cast<float2*>(
                      &g_pairs4[((size_t)(n >> 1) * N_THETA + a) * PAIR_STRIDE])
                  + (n & 1);
    for (int j = tid; j < PAIR_STRIDE; j += 192)
        out[2 * j] = make_float2(ys[j], ys[j + 1] - ys[j]);
}

// ---------------------------------------------------------------------------
// Stage 2: backprojection. One thread = one pixel x two batches x 90 angles.
// Block (32,8), grid (8, 32, 4): z = 2*g + h (batch group g, angle half h).
// ---------------------------------------------------------------------------
__global__ __launch_bounds__(256) void backproj_kernel(
    const __grid_constant__ TrigArgs trig)
{
    const int g  = blockIdx.z >> 1;                      // batch group
    const int h  = blockIdx.z & 1;                       // angle half
    const int xg = blockIdx.x * 32 + threadIdx.x;        // output col 0..255
    const int yg = blockIdx.y * 8  + threadIdx.y;        // output row 0..255

    // grid coords relative to center: (idx + 53) - 181 = idx - 128
    const float px = (float)(xg - 128);
    const float py = (float)(yg - 128);

    float acc0 = 0.0f, acc1 = 0.0f;
    const float4* __restrict__ col =
        g_pairs4 + ((size_t)g * N_THETA + (size_t)h * 90) * PAIR_STRIDE;
    const int a0 = h * 90;

    #pragma unroll 5
    for (int k = 0; k < 90; k++) {
        const float2 cs = trig.cs[a0 + k];               // const bank
        const float pos = fmaf(px, cs.x, fmaf(-py, cs.y, 181.0f));
        const int   i   = __float2int_rd(pos);           // in [-1, 362]
        const float f   = pos - (float)i;
        const float4 v  = __ldg(&col[i + 1]);            // (y0,dy0,y1,dy1)
        acc0 = fmaf(f, v.y, acc0 + v.x);
        acc1 = fmaf(f, v.w, acc1 + v.z);
        col += PAIR_STRIDE;
    }

    g_partial[g][h][(size_t)yg * OUT_W + xg] = make_float2(acc0, acc1);
}

// ---------------------------------------------------------------------------
// Stage 3: combine the two angle halves + scale. 65536 threads, 1 pix each.
// ---------------------------------------------------------------------------
__global__ __launch_bounds__(256) void combine_kernel(float* __restrict__ out)
{
    const int pix = blockIdx.x * 256 + threadIdx.x;
    const float SCALE = (float)(PI_D / 360.0);           // pi / (2*180)

    const float2 p00 = g_partial[0][0][pix];
    const float2 p01 = g_partial[0][1][pix];
    const float2 p10 = g_partial[1][0][pix];
    const float2 p11 = g_partial[1][1][pix];

    out[0 * N_PIX + pix] = (p00.x + p01.x) * SCALE;
    out[1 * N_PIX + pix] = (p00.y + p01.y) * SCALE;
    out[2 * N_PIX + pix] = (p10.x + p11.x) * SCALE;
    out[3 * N_PIX + pix] = (p10.y + p11.y) * SCALE;
}

// ---------------------------------------------------------------------------
extern "C" void kernel_launch(void* const* d_in, const int* in_sizes, int n_in,
                              void* d_out, int out_size)
{
    const float* x = (const float*)d_in[0];
    float* out = (float*)d_out;

    TrigArgs trig;
    for (int a = 0; a < N_THETA; a++) {
        double th = (double)a * (PI_D / 180.0);
        trig.cs[a] = make_float2((float)cos(th), (float)sin(th));
    }

    filter_kernel<<<dim3(N_THETA, N_BATCH), 192>>>(x);
    backproj_kernel<<<dim3(OUT_W / 32, OUT_W / 8, 4), dim3(32, 8, 1)>>>(trig);
    combine_kernel<<<N_PIX / 256, 256>>>(out);
}